// round 4
// baseline (speedup 1.0000x reference)
#include <cuda_runtime.h>
#include <cuda_bf16.h>

// Fused CrossEntropy + (LUT-remapped) BCE loss.
//
// Key identity: LUT values are exactly {0,1}, so torch-style BCE with
// -100 log clamp reduces to 100 * [b_pred != b_tgt] per sample.
// loss = ( sum_i (logsumexp(pred_i) - pred_i[tgt_i]) + 100 * n_mismatch ) / N
//
// Harness materializes the int64 target as int32, so target is const int*.
// Each thread processes TWO rows (80 bytes = 5x float4, 16B-aligned).

__device__ double g_acc;  // global accumulator (sum of ce + 100*mismatch)

__global__ void zero_acc_kernel() {
    g_acc = 0.0;
}

__device__ __forceinline__ float row_loss(const float* __restrict__ v, int tgt) {
    // safety clamp: never index v[] out of bounds even on dtype surprise
    tgt = (tgt < 0) ? 0 : ((tgt > 9) ? 9 : tgt);

    // max + argmax (first occurrence on ties, matching jnp.argmax)
    float m = v[0];
    int amax = 0;
#pragma unroll
    for (int j = 1; j < 10; j++) {
        if (v[j] > m) { m = v[j]; amax = j; }
    }

    // logsumexp
    float s = 0.0f;
#pragma unroll
    for (int j = 0; j < 10; j++) {
        s += __expf(v[j] - m);
    }
    const float lse = m + __logf(s);

    const float ce = lse - v[tgt];

    // LUT[c] = 1 iff 2 <= c <= 7
    const int bp = (amax >= 2) & (amax <= 7);
    const int bt = (tgt  >= 2) & (tgt  <= 7);

    return ce + ((bp != bt) ? 100.0f : 0.0f);
}

__global__ void __launch_bounds__(256) loss_kernel(
    const float* __restrict__ pred,
    const int* __restrict__ target,
    int n_rows)
{
    const int i  = blockIdx.x * blockDim.x + threadIdx.x;  // pair index
    const int r0 = 2 * i;

    float local = 0.0f;
    if (r0 + 1 < n_rows) {
        // Pair of rows: 80 bytes starting at byte offset 80*i -> 16B aligned.
        const float4* __restrict__ p =
            reinterpret_cast<const float4*>(pred + (size_t)i * 20);
        float e[20];
        float4 q0 = p[0];
        float4 q1 = p[1];
        float4 q2 = p[2];
        float4 q3 = p[3];
        float4 q4 = p[4];
        e[0]=q0.x; e[1]=q0.y; e[2]=q0.z; e[3]=q0.w;
        e[4]=q1.x; e[5]=q1.y; e[6]=q1.z; e[7]=q1.w;
        e[8]=q2.x; e[9]=q2.y; e[10]=q2.z; e[11]=q2.w;
        e[12]=q3.x; e[13]=q3.y; e[14]=q3.z; e[15]=q3.w;
        e[16]=q4.x; e[17]=q4.y; e[18]=q4.z; e[19]=q4.w;

        // Two targets with one 8-byte load (offset 8*i, aligned).
        const int2 t2 = *reinterpret_cast<const int2*>(target + (size_t)2 * i);

        local = row_loss(e, t2.x) + row_loss(e + 10, t2.y);
    } else if (r0 < n_rows) {
        // odd tail: single row, scalar-safe path (float2 loads, 8B aligned)
        const float2* __restrict__ p =
            reinterpret_cast<const float2*>(pred + (size_t)r0 * 10);
        float v[10];
#pragma unroll
        for (int j = 0; j < 5; j++) {
            float2 t = p[j];
            v[2 * j] = t.x;
            v[2 * j + 1] = t.y;
        }
        local = row_loss(v, target[r0]);
    }

    // --- block reduction: warp shuffle -> shared -> one double atomic ---
    __shared__ float warp_sums[8];  // 256 threads = 8 warps

#pragma unroll
    for (int off = 16; off > 0; off >>= 1)
        local += __shfl_down_sync(0xFFFFFFFFu, local, off);

    const int lane = threadIdx.x & 31;
    const int wid  = threadIdx.x >> 5;
    if (lane == 0) warp_sums[wid] = local;
    __syncthreads();

    if (wid == 0) {
        float blk = (lane < 8) ? warp_sums[lane] : 0.0f;
#pragma unroll
        for (int off = 4; off > 0; off >>= 1)
            blk += __shfl_down_sync(0xFFFFFFFFu, blk, off);
        if (lane == 0)
            atomicAdd(&g_acc, (double)blk);
    }
}

__global__ void finalize_kernel(float* out, int n_rows) {
    out[0] = (float)(g_acc / (double)n_rows);
}

extern "C" void kernel_launch(void* const* d_in, const int* in_sizes, int n_in,
                              void* d_out, int out_size) {
    const float* pred   = (const float*)d_in[0];
    const int*   target = (const int*)d_in[1];
    float*       out    = (float*)d_out;

    const int n_rows = in_sizes[1];  // target element count = N
    const int n_pairs = (n_rows + 1) / 2;

    zero_acc_kernel<<<1, 1>>>();

    const int threads = 256;
    const int blocks = (n_pairs + threads - 1) / threads;
    loss_kernel<<<blocks, threads>>>(pred, target, n_rows);

    finalize_kernel<<<1, 1>>>(out, n_rows);
}